// round 12
// baseline (speedup 1.0000x reference)
#include <cuda_runtime.h>
#include <cstdint>

// ExtractLearnableSlices — TMA bulk loads with SPLIT barriers (2+2 batches)
// so the first epilogue half overlaps the second half's copies.
//   x: (B=64, C=64, L=16384) f32
//   channel_params/offset_params: (128,) f32
//   out: (B=64, N=128, W=512) f32

#define B_DIM   64
#define C_DIM   64
#define L_DIM   16384
#define N_HEADS 128
#define WIDTH   512
#define THREADS 128
#define NB      4
#define WIN     520                 // floats per window
#define WIN_B   (WIN * 4)           // 2080 bytes, multiple of 16

__device__ __forceinline__ uint32_t smem_u32(const void* p) {
    uint64_t t;
    asm("cvta.to.shared.u64 %0, %1;" : "=l"(t) : "l"(p));
    return (uint32_t)t;
}

__device__ __forceinline__ void mbar_wait_acq(uint32_t addr) {
    uint32_t done;
    asm volatile(
        "{\n\t.reg .pred p;\n\t"
        "mbarrier.try_wait.parity.acquire.cta.shared::cta.b64 p, [%1], 0;\n\t"
        "selp.b32 %0, 1, 0, p;\n\t}"
        : "=r"(done) : "r"(addr) : "memory");
    while (!done) {
        asm volatile(
            "{\n\t.reg .pred p;\n\t"
            "mbarrier.try_wait.parity.acquire.cta.shared::cta.b64 p, [%1], 0, 0x989680;\n\t"
            "selp.b32 %0, 1, 0, p;\n\t}"
            : "=r"(done) : "r"(addr) : "memory");
    }
}

__global__ __launch_bounds__(THREADS) void extract_slices_kernel(
    const float* __restrict__ x,
    const float* __restrict__ channel_params,
    const float* __restrict__ offset_params,
    float* __restrict__ out)
{
    // win[bb][0] = floor-channel window, win[bb][1] = ceil-channel window
    __shared__ __align__(16) float win[NB][2][WIN];
    __shared__ __align__(8) uint64_t mbar[2];

    const int tid = threadIdx.x;        // 0..127
    const int i   = blockIdx.x;         // head
    const int b0  = blockIdx.y * NB;    // first batch

    const uint32_t mb0 = smem_u32(&mbar[0]);
    const uint32_t mb1 = smem_u32(&mbar[1]);

    if (tid == 0) {
        asm volatile("mbarrier.init.shared.b64 [%0], 1;" :: "r"(mb0) : "memory");
        asm volatile("mbarrier.init.shared.b64 [%0], 1;" :: "r"(mb1) : "memory");
    }
    __syncthreads();

    // ---- per-head params (exact same math as all passing rounds) ----
    const float cp = __ldg(&channel_params[i]);
    const float op = __ldg(&offset_params[i]);

    const float sc      = 1.0f / (1.0f + expf(-cp));
    const float desired = sc * (float)(C_DIM - 1);   // > 0
    const int   fc      = (int)desired;              // floor (positive)
    const int   cc      = min(fc + 1, C_DIM - 1);
    const float wc      = desired - (float)fc;

    const float so  = 1.0f / (1.0f + expf(-op));
    const float t0  = so * (float)(L_DIM - WIDTH);   // > 0
    const int   pf0 = (int)t0;                       // floor (positive)
    const int   l0  = (pf0 - 1) & ~3;                // 16B-aligned origin

    const int xfo = fc * L_DIM + l0;
    const int xco = cc * L_DIM + l0;

    // ---- issue all 8 bulk copies (2 batches per barrier phase) ----
    if (tid == 0) {
        asm volatile("mbarrier.arrive.expect_tx.shared.b64 _, [%0], %1;"
                     :: "r"(mb0), "r"((uint32_t)(2 * 2 * WIN_B)) : "memory");
        asm volatile("mbarrier.arrive.expect_tx.shared.b64 _, [%0], %1;"
                     :: "r"(mb1), "r"((uint32_t)(2 * 2 * WIN_B)) : "memory");
        #pragma unroll
        for (int bb = 0; bb < NB; ++bb) {
            const uint32_t mb = (bb < 2) ? mb0 : mb1;
            const size_t base = (size_t)(b0 + bb) * (size_t)(C_DIM * L_DIM);
            const float* srcf = x + base + xfo;
            const float* srcc = x + base + xco;
            const uint32_t df = smem_u32(&win[bb][0][0]);
            const uint32_t dc = smem_u32(&win[bb][1][0]);
            asm volatile(
                "cp.async.bulk.shared::cta.global.mbarrier::complete_tx::bytes "
                "[%0], [%1], %2, [%3];"
                :: "r"(df), "l"(srcf), "r"((uint32_t)WIN_B), "r"(mb) : "memory");
            asm volatile(
                "cp.async.bulk.shared::cta.global.mbarrier::complete_tx::bytes "
                "[%0], [%1], %2, [%3];"
                :: "r"(dc), "l"(srcc), "r"((uint32_t)WIN_B), "r"(mb) : "memory");
        }
    }

    // ---- hoisted epilogue prep (independent of TMA data) ----
    float wt[4]; int idx[4];
    #pragma unroll
    for (int k = 0; k < 4; ++k) {
        const int   j   = tid + k * THREADS;
        const float pos = t0 + (float)j;       // exact ref f32 math
        const int   pf  = (int)pos;            // floor (positive)
        wt[k]  = pos - (float)pf;
        idx[k] = pf - l0;                      // in [0, 517]
    }
    const size_t ostride = (size_t)N_HEADS * WIDTH;
    float* __restrict__ obase = out + ((size_t)b0 * N_HEADS + i) * WIDTH + tid;

    // ---- phase 0: batches 0,1 (overlaps batches 2,3 copies) ----
    mbar_wait_acq(mb0);
    #pragma unroll
    for (int bb = 0; bb < 2; ++bb) {
        const float* __restrict__ wf = win[bb][0];
        const float* __restrict__ wcv = win[bb][1];
        float* __restrict__ o = obase + bb * ostride;
        #pragma unroll
        for (int k = 0; k < 4; ++k) {
            const float a0 = wf[idx[k]];
            const float a1 = wf[idx[k] + 1];
            const float c0 = wcv[idx[k]];
            const float c1 = wcv[idx[k] + 1];
            const float v0 = a0 + wc * (c0 - a0);
            const float v1 = a1 + wc * (c1 - a1);
            o[k * THREADS] = v0 + wt[k] * (v1 - v0);
        }
    }

    // ---- phase 1: batches 2,3 ----
    mbar_wait_acq(mb1);
    #pragma unroll
    for (int bb = 2; bb < 4; ++bb) {
        const float* __restrict__ wf = win[bb][0];
        const float* __restrict__ wcv = win[bb][1];
        float* __restrict__ o = obase + bb * ostride;
        #pragma unroll
        for (int k = 0; k < 4; ++k) {
            const float a0 = wf[idx[k]];
            const float a1 = wf[idx[k] + 1];
            const float c0 = wcv[idx[k]];
            const float c1 = wcv[idx[k] + 1];
            const float v0 = a0 + wc * (c0 - a0);
            const float v1 = a1 + wc * (c1 - a1);
            o[k * THREADS] = v0 + wt[k] * (v1 - v0);
        }
    }
}

extern "C" void kernel_launch(void* const* d_in, const int* in_sizes, int n_in,
                              void* d_out, int out_size)
{
    const float* x  = (const float*)d_in[0];
    const float* ch = (const float*)d_in[1];
    const float* of = (const float*)d_in[2];
    float* out = (float*)d_out;

    dim3 grid(N_HEADS, B_DIM / NB);
    extract_slices_kernel<<<grid, THREADS>>>(x, ch, of, out);
}

// round 13
// speedup vs baseline: 1.2518x; 1.2518x over previous
#include <cuda_runtime.h>
#include <cstdint>

// ExtractLearnableSlices — deep TMA pipeline: 8 batches/block, 4 barrier
// phases of 2 batches, 256 threads.
//   x: (B=64, C=64, L=16384) f32
//   channel_params/offset_params: (128,) f32
//   out: (B=64, N=128, W=512) f32

#define B_DIM   64
#define C_DIM   64
#define L_DIM   16384
#define N_HEADS 128
#define WIDTH   512
#define THREADS 256
#define NB      8                   // batches per block
#define NPHASE  4                   // 2 batches per phase
#define WIN     520                 // floats per window
#define WIN_B   (WIN * 4)           // 2080 bytes, multiple of 16

__device__ __forceinline__ uint32_t smem_u32(const void* p) {
    uint64_t t;
    asm("cvta.to.shared.u64 %0, %1;" : "=l"(t) : "l"(p));
    return (uint32_t)t;
}

__device__ __forceinline__ void mbar_wait_acq(uint32_t addr) {
    uint32_t done;
    asm volatile(
        "{\n\t.reg .pred p;\n\t"
        "mbarrier.try_wait.parity.acquire.cta.shared::cta.b64 p, [%1], 0;\n\t"
        "selp.b32 %0, 1, 0, p;\n\t}"
        : "=r"(done) : "r"(addr) : "memory");
    while (!done) {
        asm volatile(
            "{\n\t.reg .pred p;\n\t"
            "mbarrier.try_wait.parity.acquire.cta.shared::cta.b64 p, [%1], 0, 0x989680;\n\t"
            "selp.b32 %0, 1, 0, p;\n\t}"
            : "=r"(done) : "r"(addr) : "memory");
    }
}

__global__ __launch_bounds__(THREADS) void extract_slices_kernel(
    const float* __restrict__ x,
    const float* __restrict__ channel_params,
    const float* __restrict__ offset_params,
    float* __restrict__ out)
{
    // win[bb][0] = floor-channel window, win[bb][1] = ceil-channel window
    __shared__ __align__(16) float win[NB][2][WIN];
    __shared__ __align__(8) uint64_t mbar[NPHASE];

    const int tid = threadIdx.x;        // 0..255
    const int i   = blockIdx.x;         // head
    const int b0  = blockIdx.y * NB;    // first batch

    uint32_t mb[NPHASE];
    #pragma unroll
    for (int p = 0; p < NPHASE; ++p) mb[p] = smem_u32(&mbar[p]);

    if (tid == 0) {
        #pragma unroll
        for (int p = 0; p < NPHASE; ++p)
            asm volatile("mbarrier.init.shared.b64 [%0], 1;" :: "r"(mb[p]) : "memory");
    }
    __syncthreads();

    // ---- per-head params (exact same math as all passing rounds) ----
    const float cp = __ldg(&channel_params[i]);
    const float op = __ldg(&offset_params[i]);

    const float sc      = 1.0f / (1.0f + expf(-cp));
    const float desired = sc * (float)(C_DIM - 1);   // > 0
    const int   fc      = (int)desired;              // floor (positive)
    const int   cc      = min(fc + 1, C_DIM - 1);
    const float wc      = desired - (float)fc;

    const float so  = 1.0f / (1.0f + expf(-op));
    const float t0  = so * (float)(L_DIM - WIDTH);   // > 0
    const int   pf0 = (int)t0;                       // floor (positive)
    const int   l0  = (pf0 - 1) & ~3;                // 16B-aligned origin

    const int xfo = fc * L_DIM + l0;
    const int xco = cc * L_DIM + l0;

    // ---- issue all 16 bulk copies (2 batches per phase, in phase order) ----
    if (tid == 0) {
        #pragma unroll
        for (int p = 0; p < NPHASE; ++p)
            asm volatile("mbarrier.arrive.expect_tx.shared.b64 _, [%0], %1;"
                         :: "r"(mb[p]), "r"((uint32_t)(2 * 2 * WIN_B)) : "memory");
        #pragma unroll
        for (int bb = 0; bb < NB; ++bb) {
            const uint32_t m = mb[bb >> 1];
            const size_t base = (size_t)(b0 + bb) * (size_t)(C_DIM * L_DIM);
            const float* srcf = x + base + xfo;
            const float* srcc = x + base + xco;
            const uint32_t df = smem_u32(&win[bb][0][0]);
            const uint32_t dc = smem_u32(&win[bb][1][0]);
            asm volatile(
                "cp.async.bulk.shared::cta.global.mbarrier::complete_tx::bytes "
                "[%0], [%1], %2, [%3];"
                :: "r"(df), "l"(srcf), "r"((uint32_t)WIN_B), "r"(m) : "memory");
            asm volatile(
                "cp.async.bulk.shared::cta.global.mbarrier::complete_tx::bytes "
                "[%0], [%1], %2, [%3];"
                :: "r"(dc), "l"(srcc), "r"((uint32_t)WIN_B), "r"(m) : "memory");
        }
    }

    // ---- hoisted epilogue prep (independent of TMA data) ----
    float wt[2]; int idx[2];
    #pragma unroll
    for (int k = 0; k < 2; ++k) {
        const int   j   = tid + k * THREADS;
        const float pos = t0 + (float)j;       // exact ref f32 math
        const int   pf  = (int)pos;            // floor (positive)
        wt[k]  = pos - (float)pf;
        idx[k] = pf - l0;                      // in [0, 517]
    }
    const size_t ostride = (size_t)N_HEADS * WIDTH;
    float* __restrict__ obase = out + ((size_t)b0 * N_HEADS + i) * WIDTH + tid;

    // ---- 4 phases: wait, then 2 batches x 2 j-positions each ----
    #pragma unroll
    for (int p = 0; p < NPHASE; ++p) {
        mbar_wait_acq(mb[p]);
        #pragma unroll
        for (int q = 0; q < 2; ++q) {
            const int bb = 2 * p + q;
            const float* __restrict__ wf  = win[bb][0];
            const float* __restrict__ wcv = win[bb][1];
            float* __restrict__ o = obase + bb * ostride;
            #pragma unroll
            for (int k = 0; k < 2; ++k) {
                const float a0 = wf[idx[k]];
                const float a1 = wf[idx[k] + 1];
                const float c0 = wcv[idx[k]];
                const float c1 = wcv[idx[k] + 1];
                const float v0 = a0 + wc * (c0 - a0);
                const float v1 = a1 + wc * (c1 - a1);
                o[k * THREADS] = v0 + wt[k] * (v1 - v0);
            }
        }
    }
}

extern "C" void kernel_launch(void* const* d_in, const int* in_sizes, int n_in,
                              void* d_out, int out_size)
{
    const float* x  = (const float*)d_in[0];
    const float* ch = (const float*)d_in[1];
    const float* of = (const float*)d_in[2];
    float* out = (float*)d_out;

    dim3 grid(N_HEADS, B_DIM / NB);
    extract_slices_kernel<<<grid, THREADS>>>(x, ch, of, out);
}